// round 1
// baseline (speedup 1.0000x reference)
#include <cuda_runtime.h>

#define BATCH   8
#define C       384
#define M4      1536        // 4*C
#define NZ      256         // 16*16
#define NX      1024        // 32*32
#define NHEADS  12
#define DHEAD   32

// ---------------------------------------------------------------------------
// Scratch (static device globals; no runtime allocation allowed)
// ---------------------------------------------------------------------------
__device__ float g_qkvo_z[BATCH * M4 * NZ];   //  3.1M floats
__device__ float g_qkvo_x[BATCH * M4 * NX];   // 12.6M floats
__device__ float g_lepe_z[BATCH * C * NZ];
__device__ float g_lepe_x[BATCH * C * NX];
__device__ float g_att_z [BATCH * C * NZ];
__device__ float g_att_x [BATCH * C * NX];

// ---------------------------------------------------------------------------
// GEMM: qkvo = W_qkvo (1536x384) @ feat (384 x HW) + bias, per batch
// grid (HW/64, 1536/64, B), block 256, 64x64 tile, 4x4 microtile
// ---------------------------------------------------------------------------
__global__ __launch_bounds__(256) void gemm_qkvo_kernel(
    const float* __restrict__ feat, const float* __restrict__ W,
    const float* __restrict__ bias, float* __restrict__ out, int HW)
{
    __shared__ float As[16][64];
    __shared__ float Bs[16][64];

    const int b  = blockIdx.z;
    const int m0 = blockIdx.y * 64;
    const int n0 = blockIdx.x * 64;
    const int t  = threadIdx.x;
    const int tx = t & 15;        // n dim
    const int ty = t >> 4;        // m dim

    const float* fb = feat + (size_t)b * C * HW;

    const int a_mm = t >> 2;
    const int a_kk = (t & 3) * 4;
    const int b_kk = t >> 4;
    const int b_nn = (t & 15) * 4;

    float acc[4][4];
#pragma unroll
    for (int i = 0; i < 4; i++)
#pragma unroll
        for (int j = 0; j < 4; j++) acc[i][j] = 0.f;

    for (int k0 = 0; k0 < C; k0 += 16) {
        float4 w4 = *(const float4*)(W  + (size_t)(m0 + a_mm) * C + k0 + a_kk);
        float4 f4 = *(const float4*)(fb + (size_t)(k0 + b_kk) * HW + n0 + b_nn);
        __syncthreads();
        As[a_kk + 0][a_mm] = w4.x;
        As[a_kk + 1][a_mm] = w4.y;
        As[a_kk + 2][a_mm] = w4.z;
        As[a_kk + 3][a_mm] = w4.w;
        *(float4*)&Bs[b_kk][b_nn] = f4;
        __syncthreads();
#pragma unroll
        for (int kk = 0; kk < 16; kk++) {
            float4 av = *(const float4*)&As[kk][ty * 4];
            float4 bv = *(const float4*)&Bs[kk][tx * 4];
            float a[4] = {av.x, av.y, av.z, av.w};
            float bb[4] = {bv.x, bv.y, bv.z, bv.w};
#pragma unroll
            for (int i = 0; i < 4; i++)
#pragma unroll
                for (int j = 0; j < 4; j++) acc[i][j] += a[i] * bb[j];
        }
    }

#pragma unroll
    for (int i = 0; i < 4; i++) {
        int m = m0 + ty * 4 + i;
        float bv = bias[m];
        float4 o4 = make_float4(acc[i][0] + bv, acc[i][1] + bv,
                                acc[i][2] + bv, acc[i][3] + bv);
        *(float4*)(out + ((size_t)b * M4 + m) * HW + n0 + tx * 4) = o4;
    }
}

// ---------------------------------------------------------------------------
// Depthwise 5x5 conv (pad 2) on v channels (2C..3C) of qkvo
// grid (B*C), block 256; one (b,c) plane per block
// ---------------------------------------------------------------------------
__global__ __launch_bounds__(256) void dwconv_kernel(
    const float* __restrict__ qkvo, const float* __restrict__ Wl,
    const float* __restrict__ bl, float* __restrict__ out, int Hd, int Wd)
{
    __shared__ float tile[36 * 36];
    __shared__ float wsm[25];

    const int plane = blockIdx.x;
    const int b = plane / C;
    const int c = plane % C;
    const int HW = Hd * Wd;
    const float* src = qkvo + ((size_t)b * M4 + 2 * C + c) * HW;
    float* dst = out + ((size_t)b * C + c) * HW;
    const int t = threadIdx.x;

    if (t < 25) wsm[t] = Wl[c * 25 + t];

    const int Wp = Wd + 4;
    const int Hp = Hd + 4;
    for (int idx = t; idx < Hp * Wp; idx += 256) {
        int y  = idx / Wp - 2;
        int xq = idx % Wp - 2;
        float v = 0.f;
        if (y >= 0 && y < Hd && xq >= 0 && xq < Wd) v = src[y * Wd + xq];
        tile[idx] = v;
    }
    __syncthreads();

    float bb = bl[c];
    for (int idx = t; idx < HW; idx += 256) {
        int y  = idx / Wd;
        int xq = idx % Wd;
        float s = bb;
#pragma unroll
        for (int ky = 0; ky < 5; ky++)
#pragma unroll
            for (int kx = 0; kx < 5; kx++)
                s += wsm[ky * 5 + kx] * tile[(y + ky) * Wp + (xq + kx)];
        dst[idx] = s;
    }
}

// ---------------------------------------------------------------------------
// Flash attention over the 1280-token concat(z,x) sequence.
// grid (10, B*NHEADS), block 128: 1 query per thread, KV tiles of 32 tokens.
// Reads g_qkvo_{z,x}, writes g_att_{z,x} in (b, c, n) spatial layout.
// ---------------------------------------------------------------------------
__global__ __launch_bounds__(128) void attention_kernel()
{
    __shared__ float Ks[32 * 36];   // [j][dc], row stride 36 (144B, 16B aligned)
    __shared__ float Vs[32 * 36];

    const int bh = blockIdx.y;
    const int b  = bh / NHEADS;
    const int h  = bh % NHEADS;
    const int tid = threadIdx.x;
    const int nq = blockIdx.x * 128 + tid;
    const float scale = 0.17677669529663687f;   // 1/sqrt(32)

    // load query row (coalesced per-dc: lanes read consecutive n)
    float q[32];
    {
        const float* qb; int HW, nl;
        if (nq < NZ) { qb = g_qkvo_z + ((size_t)b * M4 + h * DHEAD) * NZ; HW = NZ; nl = nq; }
        else         { qb = g_qkvo_x + ((size_t)b * M4 + h * DHEAD) * NX; HW = NX; nl = nq - NZ; }
#pragma unroll
        for (int dc = 0; dc < 32; dc++) q[dc] = qb[(size_t)dc * HW + nl] * scale;
    }

    float m = -1e30f, l = 0.f;
    float acc[32];
#pragma unroll
    for (int dc = 0; dc < 32; dc++) acc[dc] = 0.f;

    for (int tkv = 0; tkv < 40; tkv++) {
        const int n0 = tkv * 32;
        const float* kb; const float* vb; int HW, nl0;
        if (n0 < NZ) {
            HW = NZ; nl0 = n0;
            kb = g_qkvo_z + ((size_t)b * M4 +     C + h * DHEAD) * NZ;
            vb = g_qkvo_z + ((size_t)b * M4 + 2 * C + h * DHEAD) * NZ;
        } else {
            HW = NX; nl0 = n0 - NZ;
            kb = g_qkvo_x + ((size_t)b * M4 +     C + h * DHEAD) * NX;
            vb = g_qkvo_x + ((size_t)b * M4 + 2 * C + h * DHEAD) * NX;
        }
        __syncthreads();
        for (int idx = tid; idx < 1024; idx += 128) {
            int dc = idx >> 5, j = idx & 31;     // coalesced along j
            Ks[j * 36 + dc] = kb[(size_t)dc * HW + nl0 + j];
            Vs[j * 36 + dc] = vb[(size_t)dc * HW + nl0 + j];
        }
        __syncthreads();

        float s[32];
        float tmax = m;
#pragma unroll
        for (int j = 0; j < 32; j++) {
            const float4* kr = (const float4*)&Ks[j * 36];
            float sv = 0.f;
#pragma unroll
            for (int d4 = 0; d4 < 8; d4++) {
                float4 k4 = kr[d4];
                sv += q[4 * d4 + 0] * k4.x;
                sv += q[4 * d4 + 1] * k4.y;
                sv += q[4 * d4 + 2] * k4.z;
                sv += q[4 * d4 + 3] * k4.w;
            }
            s[j] = sv;
            tmax = fmaxf(tmax, sv);
        }
        float corr = __expf(m - tmax);
        m = tmax;
        l *= corr;
#pragma unroll
        for (int dc = 0; dc < 32; dc++) acc[dc] *= corr;
#pragma unroll
        for (int j = 0; j < 32; j++) {
            float p = __expf(s[j] - m);
            l += p;
            const float4* vr = (const float4*)&Vs[j * 36];
#pragma unroll
            for (int d4 = 0; d4 < 8; d4++) {
                float4 v4 = vr[d4];
                acc[4 * d4 + 0] += p * v4.x;
                acc[4 * d4 + 1] += p * v4.y;
                acc[4 * d4 + 2] += p * v4.z;
                acc[4 * d4 + 3] += p * v4.w;
            }
        }
    }

    const float inv = 1.f / l;
    float* ob; int HW, nl;
    if (nq < NZ) { ob = g_att_z + ((size_t)b * C + h * DHEAD) * NZ; HW = NZ; nl = nq; }
    else         { ob = g_att_x + ((size_t)b * C + h * DHEAD) * NX; HW = NX; nl = nq - NZ; }
#pragma unroll
    for (int dc = 0; dc < 32; dc++) ob[(size_t)dc * HW + nl] = acc[dc] * inv;
}

// ---------------------------------------------------------------------------
// Proj GEMM with fused (att + lepe) * o prologue.
// out[b][co][n] = sum_c Wp[co][c] * ((att+lepe)*o)[b][c][n] + bp[co]
// grid (HW/64, 384/64, B), block 256
// ---------------------------------------------------------------------------
__global__ __launch_bounds__(256) void gemm_proj_kernel(
    const float* __restrict__ att, const float* __restrict__ lepe,
    const float* __restrict__ qkvo, const float* __restrict__ Wp,
    const float* __restrict__ bias, float* __restrict__ out, int HW)
{
    __shared__ float As[16][64];
    __shared__ float Bs[16][64];

    const int b  = blockIdx.z;
    const int m0 = blockIdx.y * 64;
    const int n0 = blockIdx.x * 64;
    const int t  = threadIdx.x;
    const int tx = t & 15;
    const int ty = t >> 4;

    const int a_mm = t >> 2;
    const int a_kk = (t & 3) * 4;
    const int b_kk = t >> 4;
    const int b_nn = (t & 15) * 4;

    float acc[4][4];
#pragma unroll
    for (int i = 0; i < 4; i++)
#pragma unroll
        for (int j = 0; j < 4; j++) acc[i][j] = 0.f;

    for (int k0 = 0; k0 < C; k0 += 16) {
        float4 w4 = *(const float4*)(Wp + (size_t)(m0 + a_mm) * C + k0 + a_kk);
        size_t boff = ((size_t)b * C + k0 + b_kk) * HW + n0 + b_nn;
        float4 a4 = *(const float4*)(att + boff);
        float4 l4 = *(const float4*)(lepe + boff);
        size_t ooff = ((size_t)b * M4 + 3 * C + k0 + b_kk) * HW + n0 + b_nn;
        float4 og = *(const float4*)(qkvo + ooff);
        float4 f4 = make_float4((a4.x + l4.x) * og.x, (a4.y + l4.y) * og.y,
                                (a4.z + l4.z) * og.z, (a4.w + l4.w) * og.w);
        __syncthreads();
        As[a_kk + 0][a_mm] = w4.x;
        As[a_kk + 1][a_mm] = w4.y;
        As[a_kk + 2][a_mm] = w4.z;
        As[a_kk + 3][a_mm] = w4.w;
        *(float4*)&Bs[b_kk][b_nn] = f4;
        __syncthreads();
#pragma unroll
        for (int kk = 0; kk < 16; kk++) {
            float4 av = *(const float4*)&As[kk][ty * 4];
            float4 bv = *(const float4*)&Bs[kk][tx * 4];
            float a[4] = {av.x, av.y, av.z, av.w};
            float bb[4] = {bv.x, bv.y, bv.z, bv.w};
#pragma unroll
            for (int i = 0; i < 4; i++)
#pragma unroll
                for (int j = 0; j < 4; j++) acc[i][j] += a[i] * bb[j];
        }
    }

#pragma unroll
    for (int i = 0; i < 4; i++) {
        int m = m0 + ty * 4 + i;
        float bv = bias[m];
        float4 o4 = make_float4(acc[i][0] + bv, acc[i][1] + bv,
                                acc[i][2] + bv, acc[i][3] + bv);
        *(float4*)(out + ((size_t)b * C + m) * HW + n0 + tx * 4) = o4;
    }
}

// ---------------------------------------------------------------------------
// Launch
// ---------------------------------------------------------------------------
extern "C" void kernel_launch(void* const* d_in, const int* in_sizes, int n_in,
                              void* d_out, int out_size)
{
    const float* z  = (const float*)d_in[0];
    const float* x  = (const float*)d_in[1];
    const float* Wq = (const float*)d_in[2];
    const float* bq = (const float*)d_in[3];
    const float* Wl = (const float*)d_in[4];
    const float* bl = (const float*)d_in[5];
    const float* Wp = (const float*)d_in[6];
    const float* bp = (const float*)d_in[7];
    float* out = (float*)d_out;

    float *qz, *qx, *lz, *lx, *az, *ax;
    cudaGetSymbolAddress((void**)&qz, g_qkvo_z);
    cudaGetSymbolAddress((void**)&qx, g_qkvo_x);
    cudaGetSymbolAddress((void**)&lz, g_lepe_z);
    cudaGetSymbolAddress((void**)&lx, g_lepe_x);
    cudaGetSymbolAddress((void**)&az, g_att_z);
    cudaGetSymbolAddress((void**)&ax, g_att_x);

    gemm_qkvo_kernel<<<dim3(NZ / 64, M4 / 64, BATCH), 256>>>(z, Wq, bq, qz, NZ);
    gemm_qkvo_kernel<<<dim3(NX / 64, M4 / 64, BATCH), 256>>>(x, Wq, bq, qx, NX);

    dwconv_kernel<<<BATCH * C, 256>>>(qz, Wl, bl, lz, 16, 16);
    dwconv_kernel<<<BATCH * C, 256>>>(qx, Wl, bl, lx, 32, 32);

    attention_kernel<<<dim3(10, BATCH * NHEADS), 128>>>();

    gemm_proj_kernel<<<dim3(NZ / 64, C / 64, BATCH), 256>>>(az, lz, qz, Wp, bp, out, NZ);
    gemm_proj_kernel<<<dim3(NX / 64, C / 64, BATCH), 256>>>(ax, lx, qx, Wp, bp,
                                                            out + (size_t)BATCH * C * NZ, NX);
}